// round 14
// baseline (speedup 1.0000x reference)
#include <cuda_runtime.h>
#include <cuda_fp16.h>
#include <cstdint>

#define T_TOKENS 4096
#define D_HID    2048
#define HE       1024
#define NEXP     8
#define VOCAB    100000
#define TPE      12500

// ---- device scratch (no allocs allowed) ----
__device__ int    d_counts[NEXP];
__device__ int    d_offsets[NEXP];
__device__ int    d_cursor[NEXP];
__device__ int    d_perm[T_TOKENS];
__device__ int    d_wd_done;                 // wd-chunk blocks completed (target 4096)
__device__ int    d_row_done[NEXP * 32];     // gemm1 tiles done per (e,rowblock) (target 16)
__device__ __half d_hbufh[(size_t)T_TOKENS * HE];              // 8 MB
__device__ __half d_xh[(size_t)T_TOKENS * D_HID];              // 16 MB
__device__ __half d_wguh[(size_t)NEXP * D_HID * 2 * HE];       // 64 MB [e][k][2048]
__device__ __half d_wdh[(size_t)NEXP * HE * D_HID];            // 32 MB [e][k][2048]

// ============================ PTX helpers ============================
__device__ __forceinline__ uint32_t smem_u32(const void* p) {
    uint32_t a;
    asm("{ .reg .u64 t; cvta.to.shared.u64 t, %1; cvt.u32.u64 %0, t; }" : "=r"(a) : "l"(p));
    return a;
}
__device__ __forceinline__ void mma16(float* c, const uint4& a, const uint2& b) {
    asm volatile(
        "mma.sync.aligned.m16n8k16.row.col.f32.f16.f16.f32 "
        "{%0,%1,%2,%3},{%4,%5,%6,%7},{%8,%9},{%0,%1,%2,%3};"
        : "+f"(c[0]), "+f"(c[1]), "+f"(c[2]), "+f"(c[3])
        : "r"(a.x), "r"(a.y), "r"(a.z), "r"(a.w), "r"(b.x), "r"(b.y));
}
#define LDMX4(v, addr)                                                       \
    asm volatile("ldmatrix.sync.aligned.m8n8.x4.shared.b16 {%0,%1,%2,%3}, [%4];" \
        : "=r"((v).x), "=r"((v).y), "=r"((v).z), "=r"((v).w) : "r"(addr))
#define LDMX4T(r0, r1, r2, r3, addr)                                         \
    asm volatile("ldmatrix.sync.aligned.m8n8.x4.trans.shared.b16 {%0,%1,%2,%3}, [%4];" \
        : "=r"(r0), "=r"(r1), "=r"(r2), "=r"(r3) : "r"(addr))
#define CPA16(dst, src) \
    asm volatile("cp.async.cg.shared.global [%0], [%1], 16;" :: "r"(dst), "l"(src) : "memory")
#define CP_COMMIT() asm volatile("cp.async.commit_group;" ::: "memory")
#define CP_WAIT(n)  asm volatile("cp.async.wait_group %0;" :: "n"(n) : "memory")

#define A_ROWB 80
#define B_ROWB 272
#define SLOT_A (128 * A_ROWB)      // 10240
#define SLOT_B (32 * B_ROWB)       // 8704
#define NSLOT 5
#define SMEM_TOT (NSLOT * (SLOT_A + SLOT_B))   // 94720

#define G1_TILES 4096     // 16 x 32 x 8
#define WD_BLOCKS 4096    // wd conversion spread over all gemm1 blocks

// ============================ routing (+flag reset) ============================
__global__ void route_kernel(const void* __restrict__ tok_raw) {
    __shared__ int s_is64;
    __shared__ int s_counts[NEXP];
    int tid = threadIdx.x;
    if (tid < NEXP) s_counts[tid] = 0;
    if (tid < NEXP * 32) d_row_done[tid] = 0;
    if (tid == 0) {
        d_wd_done = 0;
        const int* w = (const int*)tok_raw;
        int allz = 1;
        for (int i = 1; i < 512; i += 2) if (w[i] != 0) { allz = 0; break; }
        s_is64 = allz;
    }
    __syncthreads();
    const int is64 = s_is64;
    int eid[T_TOKENS / 256];
#pragma unroll
    for (int it = 0; it < T_TOKENS / 256; it++) {
        int t = tid + it * 256;
        long long v = is64 ? ((const long long*)tok_raw)[t] : (long long)((const int*)tok_raw)[t];
        if (v < 0) v = 0;
        if (v > VOCAB - 1) v = VOCAB - 1;
        int ex = (int)(v / TPE);
        if (ex > NEXP - 1) ex = NEXP - 1;
        eid[it] = ex;
        atomicAdd(&s_counts[ex], 1);
    }
    __syncthreads();
    if (tid == 0) {
        int off = 0;
        for (int ex = 0; ex < NEXP; ex++) {
            d_counts[ex] = s_counts[ex];
            d_offsets[ex] = off;
            d_cursor[ex] = off;
            off += s_counts[ex];
        }
    }
    __syncthreads();
#pragma unroll
    for (int it = 0; it < T_TOKENS / 256; it++) {
        int t = tid + it * 256;
        int pos = atomicAdd(&d_cursor[eid[it]], 1);
        d_perm[pos] = t;
    }
}

// ============================ converters ============================
__device__ __forceinline__ uint4 pack8(float4 a, float4 b) {
    __align__(16) __half2 h[4];
    h[0] = __floats2half2_rn(a.x, a.y); h[1] = __floats2half2_rn(a.z, a.w);
    h[2] = __floats2half2_rn(b.x, b.y); h[3] = __floats2half2_rn(b.z, b.w);
    return *(uint4*)h;
}
__global__ __launch_bounds__(256) void conv_x_kernel(const float* __restrict__ x) {
    size_t gid = (size_t)blockIdx.x * 256 + threadIdx.x;
    const float4* s = (const float4*)x + gid * 4;
    uint4* d = (uint4*)d_xh + gid * 2;
    d[0] = pack8(s[0], s[1]);
    d[1] = pack8(s[2], s[3]);
}
__global__ __launch_bounds__(256) void conv_wgu_kernel(
    const float* __restrict__ Wg, const float* __restrict__ Wu, int e0) {
    size_t gid = (size_t)e0 * D_HID * 128 + (size_t)blockIdx.x * 256 + threadIdx.x;
    size_t rowAll = gid >> 7;
    int n0 = (int)(gid & 127) * 8;
    const float4* g = (const float4*)(Wg + rowAll * HE + n0);
    const float4* u = (const float4*)(Wu + rowAll * HE + n0);
    float4 g0 = g[0], g1 = g[1], u0 = u[0], u1 = u[1];
    __align__(16) __half2 h[8];
    h[0] = __floats2half2_rn(g0.x, u0.x); h[1] = __floats2half2_rn(g0.y, u0.y);
    h[2] = __floats2half2_rn(g0.z, u0.z); h[3] = __floats2half2_rn(g0.w, u0.w);
    h[4] = __floats2half2_rn(g1.x, u1.x); h[5] = __floats2half2_rn(g1.y, u1.y);
    h[6] = __floats2half2_rn(g1.z, u1.z); h[7] = __floats2half2_rn(g1.w, u1.w);
    uint4* d = (uint4*)d_wguh + gid * 2;
    d[0] = *(uint4*)&h[0];
    d[1] = *(uint4*)&h[4];
}

// ============================================================================
// FUSED: bid < G1_TILES -> wd chunk + gemm1 tile;
//        bid >= G1_TILES -> gemm2 tile (spins on wd + its row-block counter).
// Mainloops: 5-slot ring, 2 chunks per __syncthreads.
// ============================================================================
__global__ __launch_bounds__(256, 2) void fused_kernel(
    const float* __restrict__ Wd, float* __restrict__ out)
{
    const int bid = blockIdx.x;
    const int t = threadIdx.x, lane = t & 31, w = t >> 5;
    const int wm = w & 1, wn = w >> 1;

    extern __shared__ __align__(16) char smem[];
    const uint32_t sb = smem_u32(smem);
    const uint32_t a_off = (((lane & 7) + ((lane >> 3) & 1) * 8) * A_ROWB) + (lane >> 4) * 16;
    const uint32_t b_off = (((lane & 7) + ((lane >> 3) & 1) * 8) * B_ROWB) + (lane >> 4) * 16;

    if (bid < G1_TILES) {
        // -------- wd-conversion chunk (every gemm1 block: 16 floats/thread) --------
        {
            size_t gt = (size_t)bid * 256 + t;               // [0, 1048576)
            const float4* s = (const float4*)Wd + gt * 4;
            uint4* d = (uint4*)d_wdh + gt * 2;
            d[0] = pack8(s[0], s[1]);
            d[1] = pack8(s[2], s[3]);
            __threadfence();
            __syncthreads();
            if (t == 0) atomicAdd(&d_wd_done, 1);
        }
        // -------- gemm1 tile --------
        const int e = bid >> 9;
        const int by = (bid >> 4) & 31;
        const int bx = bid & 15;
        const int cnt = d_counts[e];
        const int row0 = by * 128;
        if (row0 >= cnt) return;
        const int off = d_offsets[e];

        const int ar2 = t >> 1, ah = t & 1;
        int arr = row0 + ar2; if (arr >= cnt) arr = cnt - 1;
        const char* srcA = (const char*)(d_xh + (size_t)d_perm[off + arr] * D_HID) + ah * 32;
        const uint32_t dstA = sb + ar2 * A_ROWB + ah * 32;
        const int bk = t >> 3, bs = t & 7;
        const char* srcB = (const char*)(d_wguh + ((size_t)e * D_HID + bk) * (2 * HE) + bx * 128 + bs * 16);
        const uint32_t dstB = sb + NSLOT * SLOT_A + bk * B_ROWB + bs * 32;

        float acc[4][4][4] = {};
        const int NC = D_HID / 32;
#pragma unroll
        for (int s = 0; s < 3; s++) {
            CPA16(dstA + s * SLOT_A, srcA + s * 64);
            CPA16(dstA + s * SLOT_A + 16, srcA + s * 64 + 16);
            CPA16(dstB + s * SLOT_B, srcB + (size_t)s * 32 * (2 * HE) * 2);
            CPA16(dstB + s * SLOT_B + 16, srcB + (size_t)s * 32 * (2 * HE) * 2 + 16);
            CP_COMMIT();
        }
        int s_c0 = 0, s_c1 = 1, s_i0 = 3, s_i1 = 4;
        for (int kc = 0; kc < NC; kc += 2) {
            CP_WAIT(1);
            __syncthreads();
            const int kn0 = kc + 3, kn1 = kc + 4;
            if (kn0 < NC) {
                CPA16(dstA + s_i0 * SLOT_A, srcA + kn0 * 64);
                CPA16(dstA + s_i0 * SLOT_A + 16, srcA + kn0 * 64 + 16);
                CPA16(dstB + s_i0 * SLOT_B, srcB + (size_t)kn0 * 32 * (2 * HE) * 2);
                CPA16(dstB + s_i0 * SLOT_B + 16, srcB + (size_t)kn0 * 32 * (2 * HE) * 2 + 16);
            }
            CP_COMMIT();
            if (kn1 < NC) {
                CPA16(dstA + s_i1 * SLOT_A, srcA + kn1 * 64);
                CPA16(dstA + s_i1 * SLOT_A + 16, srcA + kn1 * 64 + 16);
                CPA16(dstB + s_i1 * SLOT_B, srcB + (size_t)kn1 * 32 * (2 * HE) * 2);
                CPA16(dstB + s_i1 * SLOT_B + 16, srcB + (size_t)kn1 * 32 * (2 * HE) * 2 + 16);
            }
            CP_COMMIT();
#pragma unroll
            for (int half = 0; half < 2; half++) {
                const int cur = half ? s_c1 : s_c0;
                const uint32_t sAc = sb + cur * SLOT_A;
                const uint32_t sBc = sb + NSLOT * SLOT_A + cur * SLOT_B;
#pragma unroll
                for (int ks = 0; ks < 2; ks++) {
                    uint4 a[4]; uint2 b[4];
#pragma unroll
                    for (int mi = 0; mi < 4; mi++)
                        LDMX4(a[mi], sAc + (wm * 4 + mi) * (16 * A_ROWB) + ks * 32 + a_off);
#pragma unroll
                    for (int j = 0; j < 2; j++) {
                        uint32_t r0, r1, r2, r3;
                        LDMX4T(r0, r1, r2, r3, sBc + ks * (16 * B_ROWB) + (wn * 4 + 2 * j) * 16 + b_off);
                        b[2 * j].x = r0;     b[2 * j].y = r1;
                        b[2 * j + 1].x = r2; b[2 * j + 1].y = r3;
                    }
#pragma unroll
                    for (int mi = 0; mi < 4; mi++)
#pragma unroll
                        for (int ni = 0; ni < 4; ni++)
                            mma16(acc[mi][ni], a[mi], b[ni]);
                }
            }
            s_c0 += 2; if (s_c0 >= NSLOT) s_c0 -= NSLOT;
            s_c1 += 2; if (s_c1 >= NSLOT) s_c1 -= NSLOT;
            s_i0 += 2; if (s_i0 >= NSLOT) s_i0 -= NSLOT;
            s_i1 += 2; if (s_i1 >= NSLOT) s_i1 -= NSLOT;
        }
        CP_WAIT(0);

        const int q = lane & 3;
#pragma unroll
        for (int mi = 0; mi < 4; mi++) {
            int r1 = row0 + wm * 64 + mi * 16 + (lane >> 2), r2 = r1 + 8;
#pragma unroll
            for (int ni = 0; ni < 4; ni++) {
                int hc = bx * 64 + wn * 16 + ni * 4 + q;
                if (r1 < cnt) {
                    float g = acc[mi][ni][0], u = acc[mi][ni][1];
                    d_hbufh[(size_t)(off + r1) * HE + hc] = __float2half_rn(g / (1.f + __expf(-g)) * u);
                }
                if (r2 < cnt) {
                    float g = acc[mi][ni][2], u = acc[mi][ni][3];
                    d_hbufh[(size_t)(off + r2) * HE + hc] = __float2half_rn(g / (1.f + __expf(-g)) * u);
                }
            }
        }
        __threadfence();
        __syncthreads();
        if (t == 0) atomicAdd(&d_row_done[(e << 5) + by], 1);
    } else {
        // -------- gemm2 tile --------
        const int bid2 = bid - G1_TILES;
        const int e = bid2 >> 9;
        const int ry = (bid2 >> 4) & 31;
        const int bx = bid2 & 15;
        const int cnt = d_counts[e];
        const int row0 = ry * 128;
        if (row0 >= cnt) return;
        const int off = d_offsets[e];

        if (t == 0) {
            while (atomicAdd(&d_wd_done, 0) < WD_BLOCKS) __nanosleep(256);
            while (atomicAdd(&d_row_done[(e << 5) + ry], 0) < 16) __nanosleep(128);
        }
        __syncthreads();
        __threadfence();

        const int ar2 = t >> 1, ah = t & 1;
        int hr = off + row0 + ar2; if (hr > T_TOKENS - 1) hr = T_TOKENS - 1;
        const char* srcA = (const char*)(d_hbufh + (size_t)hr * HE) + ah * 32;
        const uint32_t dstA = sb + ar2 * A_ROWB + ah * 32;
        const int bk = t >> 3, bs = t & 7;
        const char* srcB = (const char*)(d_wdh + ((size_t)e * HE + bk) * D_HID + bx * 128 + bs * 16);
        const uint32_t dstB = sb + NSLOT * SLOT_A + bk * B_ROWB + bs * 32;

        float acc[4][4][4] = {};
        const int NC = HE / 32;
#pragma unroll
        for (int s = 0; s < 3; s++) {
            CPA16(dstA + s * SLOT_A, srcA + s * 64);
            CPA16(dstA + s * SLOT_A + 16, srcA + s * 64 + 16);
            CPA16(dstB + s * SLOT_B, srcB + (size_t)s * 32 * D_HID * 2);
            CPA16(dstB + s * SLOT_B + 16, srcB + (size_t)s * 32 * D_HID * 2 + 16);
            CP_COMMIT();
        }
        int s_c0 = 0, s_c1 = 1, s_i0 = 3, s_i1 = 4;
        for (int kc = 0; kc < NC; kc += 2) {
            CP_WAIT(1);
            __syncthreads();
            const int kn0 = kc + 3, kn1 = kc + 4;
            if (kn0 < NC) {
                CPA16(dstA + s_i0 * SLOT_A, srcA + kn0 * 64);
                CPA16(dstA + s_i0 * SLOT_A + 16, srcA + kn0 * 64 + 16);
                CPA16(dstB + s_i0 * SLOT_B, srcB + (size_t)kn0 * 32 * D_HID * 2);
                CPA16(dstB + s_i0 * SLOT_B + 16, srcB + (size_t)kn0 * 32 * D_HID * 2 + 16);
            }
            CP_COMMIT();
            if (kn1 < NC) {
                CPA16(dstA + s_i1 * SLOT_A, srcA + kn1 * 64);
                CPA16(dstA + s_i1 * SLOT_A + 16, srcA + kn1 * 64 + 16);
                CPA16(dstB + s_i1 * SLOT_B, srcB + (size_t)kn1 * 32 * D_HID * 2);
                CPA16(dstB + s_i1 * SLOT_B + 16, srcB + (size_t)kn1 * 32 * D_HID * 2 + 16);
            }
            CP_COMMIT();
#pragma unroll
            for (int half = 0; half < 2; half++) {
                const int cur = half ? s_c1 : s_c0;
                const uint32_t sAc = sb + cur * SLOT_A;
                const uint32_t sBc = sb + NSLOT * SLOT_A + cur * SLOT_B;
#pragma unroll
                for (int ks = 0; ks < 2; ks++) {
                    uint4 a[4]; uint2 b[4];
#pragma unroll
                    for (int mi = 0; mi < 4; mi++)
                        LDMX4(a[mi], sAc + (wm * 4 + mi) * (16 * A_ROWB) + ks * 32 + a_off);
#pragma unroll
                    for (int j = 0; j < 2; j++) {
                        uint32_t r0, r1, r2, r3;
                        LDMX4T(r0, r1, r2, r3, sBc + ks * (16 * B_ROWB) + (wn * 4 + 2 * j) * 16 + b_off);
                        b[2 * j].x = r0;     b[2 * j].y = r1;
                        b[2 * j + 1].x = r2; b[2 * j + 1].y = r3;
                    }
#pragma unroll
                    for (int mi = 0; mi < 4; mi++)
#pragma unroll
                        for (int ni = 0; ni < 4; ni++)
                            mma16(acc[mi][ni], a[mi], b[ni]);
                }
            }
            s_c0 += 2; if (s_c0 >= NSLOT) s_c0 -= NSLOT;
            s_c1 += 2; if (s_c1 >= NSLOT) s_c1 -= NSLOT;
            s_i0 += 2; if (s_i0 >= NSLOT) s_i0 -= NSLOT;
            s_i1 += 2; if (s_i1 >= NSLOT) s_i1 -= NSLOT;
        }
        CP_WAIT(0);

        const int q = lane & 3;
#pragma unroll
        for (int mi = 0; mi < 4; mi++) {
            int r1 = row0 + wm * 64 + mi * 16 + (lane >> 2), r2 = r1 + 8;
#pragma unroll
            for (int ni = 0; ni < 4; ni++) {
                int col = bx * 128 + wn * 32 + ni * 8 + 2 * q;
                if (r1 < cnt) {
                    float2 v; v.x = acc[mi][ni][0]; v.y = acc[mi][ni][1];
                    *(float2*)(out + (size_t)d_perm[off + r1] * D_HID + col) = v;
                }
                if (r2 < cnt) {
                    float2 v; v.x = acc[mi][ni][2]; v.y = acc[mi][ni][3];
                    *(float2*)(out + (size_t)d_perm[off + r2] * D_HID + col) = v;
                }
            }
        }
    }
}

// ============================ launch ============================
extern "C" void kernel_launch(void* const* d_in, const int* in_sizes, int n_in,
                              void* d_out, int out_size) {
    const float* x   = (const float*)d_in[0];
    const void*  tok = d_in[1];
    const float* Wg  = (const float*)d_in[2];
    const float* Wu  = (const float*)d_in[3];
    const float* Wd  = (const float*)d_in[4];
    float* out = (float*)d_out;

    static cudaStream_t s1 = nullptr;
    static cudaEvent_t ev0 = nullptr, evWB = nullptr;
    if (!s1) {   // first call is the uncaptured correctness run
        cudaStreamCreateWithFlags(&s1, cudaStreamNonBlocking);
        cudaEventCreateWithFlags(&ev0, cudaEventDisableTiming);
        cudaEventCreateWithFlags(&evWB, cudaEventDisableTiming);
        cudaFuncSetAttribute(fused_kernel, cudaFuncAttributeMaxDynamicSharedMemorySize, SMEM_TOT);
    }

    const int WGU_GRID_HALF = (4 * D_HID * 128) / 256;

    cudaEventRecord(ev0, 0);
    cudaStreamWaitEvent(s1, ev0, 0);

    // s1: route (zeroes flags) -> wgu half B
    route_kernel<<<1, 256, 0, s1>>>(tok);
    conv_wgu_kernel<<<WGU_GRID_HALF, 256, 0, s1>>>(Wg, Wu, 4);
    cudaEventRecord(evWB, s1);

    // stream 0: conv_x, wgu half A, then the fused megakernel
    conv_x_kernel<<<(T_TOKENS * D_HID / 16) / 256, 256>>>(x);
    conv_wgu_kernel<<<WGU_GRID_HALF, 256>>>(Wg, Wu, 0);
    cudaStreamWaitEvent(0, evWB, 0);
    fused_kernel<<<2 * G1_TILES, 256, SMEM_TOT>>>(Wd, out);
}

// round 15
// speedup vs baseline: 1.0568x; 1.0568x over previous
#include <cuda_runtime.h>
#include <cuda_fp16.h>
#include <cstdint>

#define T_TOKENS 4096
#define D_HID    2048
#define HE       1024
#define NEXP     8
#define VOCAB    100000
#define TPE      12500

// ---- device scratch (no allocs allowed) ----
__device__ int    d_counts[NEXP];
__device__ int    d_offsets[NEXP];
__device__ int    d_cursor[NEXP];
__device__ int    d_perm[T_TOKENS];
__device__ int    d_wd_done;                 // wd-chunk blocks completed (target 1024)
__device__ int    d_row_done[NEXP * 32];     // gemm1 tiles done per (e,rowblock) (target 16)
__device__ __half d_hbufh[(size_t)T_TOKENS * HE];              // 8 MB
__device__ __half d_xh[(size_t)T_TOKENS * D_HID];              // 16 MB
__device__ __half d_wguh[(size_t)NEXP * D_HID * 2 * HE];       // 64 MB [e][k][2048]
__device__ __half d_wdh[(size_t)NEXP * HE * D_HID];            // 32 MB [e][k][2048]

// ============================ PTX helpers ============================
__device__ __forceinline__ uint32_t smem_u32(const void* p) {
    uint32_t a;
    asm("{ .reg .u64 t; cvta.to.shared.u64 t, %1; cvt.u32.u64 %0, t; }" : "=r"(a) : "l"(p));
    return a;
}
__device__ __forceinline__ void mma16(float* c, const uint4& a, const uint2& b) {
    asm volatile(
        "mma.sync.aligned.m16n8k16.row.col.f32.f16.f16.f32 "
        "{%0,%1,%2,%3},{%4,%5,%6,%7},{%8,%9},{%0,%1,%2,%3};"
        : "+f"(c[0]), "+f"(c[1]), "+f"(c[2]), "+f"(c[3])
        : "r"(a.x), "r"(a.y), "r"(a.z), "r"(a.w), "r"(b.x), "r"(b.y));
}
#define LDMX4(v, addr)                                                       \
    asm volatile("ldmatrix.sync.aligned.m8n8.x4.shared.b16 {%0,%1,%2,%3}, [%4];" \
        : "=r"((v).x), "=r"((v).y), "=r"((v).z), "=r"((v).w) : "r"(addr))
#define LDMX4T(r0, r1, r2, r3, addr)                                         \
    asm volatile("ldmatrix.sync.aligned.m8n8.x4.trans.shared.b16 {%0,%1,%2,%3}, [%4];" \
        : "=r"(r0), "=r"(r1), "=r"(r2), "=r"(r3) : "r"(addr))
#define CPA16(dst, src) \
    asm volatile("cp.async.cg.shared.global [%0], [%1], 16;" :: "r"(dst), "l"(src) : "memory")
#define CP_COMMIT() asm volatile("cp.async.commit_group;" ::: "memory")
#define CP_WAIT(n)  asm volatile("cp.async.wait_group %0;" :: "n"(n) : "memory")

#define A_ROWB 80
#define B_ROWB 272
#define SLOT_A (128 * A_ROWB)
#define SLOT_B (32 * B_ROWB)
#define NSTAGE 4
#define SMEM_TOT (NSTAGE * (SLOT_A + SLOT_B))   // 75776

#define G1_TILES 4096     // 16 x 32 x 8
#define WD_BLOCKS 1024    // wd conversion on the LAST 1024 gemm1 bids

// ============================ routing (+flag reset) ============================
__global__ void route_kernel(const void* __restrict__ tok_raw) {
    __shared__ int s_is64;
    __shared__ int s_counts[NEXP];
    int tid = threadIdx.x;
    if (tid < NEXP) s_counts[tid] = 0;
    if (tid < NEXP * 32) d_row_done[tid] = 0;
    if (tid == 0) {
        d_wd_done = 0;
        const int* w = (const int*)tok_raw;
        int allz = 1;
        for (int i = 1; i < 512; i += 2) if (w[i] != 0) { allz = 0; break; }
        s_is64 = allz;
    }
    __syncthreads();
    const int is64 = s_is64;
    int eid[T_TOKENS / 256];
#pragma unroll
    for (int it = 0; it < T_TOKENS / 256; it++) {
        int t = tid + it * 256;
        long long v = is64 ? ((const long long*)tok_raw)[t] : (long long)((const int*)tok_raw)[t];
        if (v < 0) v = 0;
        if (v > VOCAB - 1) v = VOCAB - 1;
        int ex = (int)(v / TPE);
        if (ex > NEXP - 1) ex = NEXP - 1;
        eid[it] = ex;
        atomicAdd(&s_counts[ex], 1);
    }
    __syncthreads();
    if (tid == 0) {
        int off = 0;
        for (int ex = 0; ex < NEXP; ex++) {
            d_counts[ex] = s_counts[ex];
            d_offsets[ex] = off;
            d_cursor[ex] = off;
            off += s_counts[ex];
        }
    }
    __syncthreads();
#pragma unroll
    for (int it = 0; it < T_TOKENS / 256; it++) {
        int t = tid + it * 256;
        int pos = atomicAdd(&d_cursor[eid[it]], 1);
        d_perm[pos] = t;
    }
}

// ============================ converters (streaming loads/stores) ============================
__device__ __forceinline__ uint4 pack8(float4 a, float4 b) {
    __align__(16) __half2 h[4];
    h[0] = __floats2half2_rn(a.x, a.y); h[1] = __floats2half2_rn(a.z, a.w);
    h[2] = __floats2half2_rn(b.x, b.y); h[3] = __floats2half2_rn(b.z, b.w);
    return *(uint4*)h;
}
__global__ __launch_bounds__(256) void conv_x_kernel(const float* __restrict__ x) {
    size_t gid = (size_t)blockIdx.x * 256 + threadIdx.x;
    const float4* s = (const float4*)x + gid * 4;
    float4 s0 = __ldcs(s), s1 = __ldcs(s + 1), s2 = __ldcs(s + 2), s3 = __ldcs(s + 3);
    uint4* d = (uint4*)d_xh + gid * 2;
    __stcs(d,     pack8(s0, s1));
    __stcs(d + 1, pack8(s2, s3));
}
__global__ __launch_bounds__(256) void conv_wgu_kernel(
    const float* __restrict__ Wg, const float* __restrict__ Wu, int e0) {
    size_t gid = (size_t)e0 * D_HID * 128 + (size_t)blockIdx.x * 256 + threadIdx.x;
    size_t rowAll = gid >> 7;
    int n0 = (int)(gid & 127) * 8;
    const float4* g = (const float4*)(Wg + rowAll * HE + n0);
    const float4* u = (const float4*)(Wu + rowAll * HE + n0);
    float4 g0 = __ldcs(g), g1 = __ldcs(g + 1), u0 = __ldcs(u), u1 = __ldcs(u + 1);
    __align__(16) __half2 h[8];
    h[0] = __floats2half2_rn(g0.x, u0.x); h[1] = __floats2half2_rn(g0.y, u0.y);
    h[2] = __floats2half2_rn(g0.z, u0.z); h[3] = __floats2half2_rn(g0.w, u0.w);
    h[4] = __floats2half2_rn(g1.x, u1.x); h[5] = __floats2half2_rn(g1.y, u1.y);
    h[6] = __floats2half2_rn(g1.z, u1.z); h[7] = __floats2half2_rn(g1.w, u1.w);
    uint4* d = (uint4*)d_wguh + gid * 2;
    __stcs(d,     *(uint4*)&h[0]);
    __stcs(d + 1, *(uint4*)&h[4]);
}

// ============================================================================
// FUSED: bid < G1_TILES -> gemm1 tile (LAST 1024 bids also convert wd first);
//        bid >= G1_TILES -> gemm2 tile (spins on wd + its row-block counter).
// Mainloops: R13's proven 4-stage, 1 chunk per __syncthreads.
// ============================================================================
__global__ __launch_bounds__(256, 2) void fused_kernel(
    const float* __restrict__ Wd, float* __restrict__ out)
{
    const int bid = blockIdx.x;
    const int t = threadIdx.x, lane = t & 31, w = t >> 5;
    const int wm = w & 1, wn = w >> 1;

    extern __shared__ __align__(16) char smem[];
    const uint32_t sb = smem_u32(smem);
    const uint32_t a_off = (((lane & 7) + ((lane >> 3) & 1) * 8) * A_ROWB) + (lane >> 4) * 16;
    const uint32_t b_off = (((lane & 7) + ((lane >> 3) & 1) * 8) * B_ROWB) + (lane >> 4) * 16;

    if (bid < G1_TILES) {
        // -------- wd-conversion chunk on the LAST 1024 gemm1 bids --------
        if (bid >= G1_TILES - WD_BLOCKS) {
            const int wb = bid - (G1_TILES - WD_BLOCKS);
#pragma unroll
            for (int i = 0; i < 4; i++) {
                size_t gid = (size_t)wb * 1024 + i * 256 + t;
                const float4* s = (const float4*)Wd + gid * 4;
                float4 s0 = __ldcs(s), s1 = __ldcs(s + 1), s2 = __ldcs(s + 2), s3 = __ldcs(s + 3);
                uint4* d = (uint4*)d_wdh + gid * 2;
                __stcs(d,     pack8(s0, s1));
                __stcs(d + 1, pack8(s2, s3));
            }
            __threadfence();
            __syncthreads();
            if (t == 0) atomicAdd(&d_wd_done, 1);
        }
        // -------- gemm1 tile --------
        const int e = bid >> 9;
        const int by = (bid >> 4) & 31;
        const int bx = bid & 15;
        const int cnt = d_counts[e];
        const int row0 = by * 128;
        if (row0 >= cnt) return;
        const int off = d_offsets[e];

        const int ar2 = t >> 1, ah = t & 1;
        int arr = row0 + ar2; if (arr >= cnt) arr = cnt - 1;
        const char* srcA = (const char*)(d_xh + (size_t)d_perm[off + arr] * D_HID) + ah * 32;
        const uint32_t dstA = sb + ar2 * A_ROWB + ah * 32;
        const int bk = t >> 3, bs = t & 7;
        const char* srcB = (const char*)(d_wguh + ((size_t)e * D_HID + bk) * (2 * HE) + bx * 128 + bs * 16);
        const uint32_t dstB = sb + NSTAGE * SLOT_A + bk * B_ROWB + bs * 32;

        float acc[4][4][4] = {};
        const int NC = D_HID / 32;
#pragma unroll
        for (int s = 0; s < NSTAGE - 1; s++) {
            CPA16(dstA + s * SLOT_A, srcA + s * 64);
            CPA16(dstA + s * SLOT_A + 16, srcA + s * 64 + 16);
            CPA16(dstB + s * SLOT_B, srcB + (size_t)s * 32 * (2 * HE) * 2);
            CPA16(dstB + s * SLOT_B + 16, srcB + (size_t)s * 32 * (2 * HE) * 2 + 16);
            CP_COMMIT();
        }
        for (int kc = 0; kc < NC; kc++) {
            CP_WAIT(NSTAGE - 2);
            __syncthreads();
            const int kn = kc + NSTAGE - 1;
            if (kn < NC) {
                const int sl = kn & (NSTAGE - 1);
                CPA16(dstA + sl * SLOT_A, srcA + kn * 64);
                CPA16(dstA + sl * SLOT_A + 16, srcA + kn * 64 + 16);
                CPA16(dstB + sl * SLOT_B, srcB + (size_t)kn * 32 * (2 * HE) * 2);
                CPA16(dstB + sl * SLOT_B + 16, srcB + (size_t)kn * 32 * (2 * HE) * 2 + 16);
            }
            CP_COMMIT();
            const int cur = kc & (NSTAGE - 1);
            const uint32_t sAc = sb + cur * SLOT_A;
            const uint32_t sBc = sb + NSTAGE * SLOT_A + cur * SLOT_B;
#pragma unroll
            for (int ks = 0; ks < 2; ks++) {
                uint4 a[4]; uint2 b[4];
#pragma unroll
                for (int mi = 0; mi < 4; mi++)
                    LDMX4(a[mi], sAc + (wm * 4 + mi) * (16 * A_ROWB) + ks * 32 + a_off);
#pragma unroll
                for (int j = 0; j < 2; j++) {
                    uint32_t r0, r1, r2, r3;
                    LDMX4T(r0, r1, r2, r3, sBc + ks * (16 * B_ROWB) + (wn * 4 + 2 * j) * 16 + b_off);
                    b[2 * j].x = r0;     b[2 * j].y = r1;
                    b[2 * j + 1].x = r2; b[2 * j + 1].y = r3;
                }
#pragma unroll
                for (int mi = 0; mi < 4; mi++)
#pragma unroll
                    for (int ni = 0; ni < 4; ni++)
                        mma16(acc[mi][ni], a[mi], b[ni]);
            }
        }
        CP_WAIT(0);

        const int q = lane & 3;
#pragma unroll
        for (int mi = 0; mi < 4; mi++) {
            int r1 = row0 + wm * 64 + mi * 16 + (lane >> 2), r2 = r1 + 8;
#pragma unroll
            for (int ni = 0; ni < 4; ni++) {
                int hc = bx * 64 + wn * 16 + ni * 4 + q;
                if (r1 < cnt) {
                    float g = acc[mi][ni][0], u = acc[mi][ni][1];
                    d_hbufh[(size_t)(off + r1) * HE + hc] = __float2half_rn(g / (1.f + __expf(-g)) * u);
                }
                if (r2 < cnt) {
                    float g = acc[mi][ni][2], u = acc[mi][ni][3];
                    d_hbufh[(size_t)(off + r2) * HE + hc] = __float2half_rn(g / (1.f + __expf(-g)) * u);
                }
            }
        }
        // publish this tile
        __threadfence();
        __syncthreads();
        if (t == 0) atomicAdd(&d_row_done[(e << 5) + by], 1);
    } else {
        // -------- gemm2 tile --------
        const int bid2 = bid - G1_TILES;
        const int e = bid2 >> 9;
        const int ry = (bid2 >> 4) & 31;
        const int bx = bid2 & 15;
        const int cnt = d_counts[e];
        const int row0 = ry * 128;
        if (row0 >= cnt) return;
        const int off = d_offsets[e];

        // wait for wd conversion + all 16 gemm1 tiles of this row-block
        if (t == 0) {
            while (atomicAdd(&d_wd_done, 0) < WD_BLOCKS) __nanosleep(256);
            while (atomicAdd(&d_row_done[(e << 5) + ry], 0) < 16) __nanosleep(128);
        }
        __syncthreads();
        __threadfence();

        const int ar2 = t >> 1, ah = t & 1;
        int hr = off + row0 + ar2; if (hr > T_TOKENS - 1) hr = T_TOKENS - 1;
        const char* srcA = (const char*)(d_hbufh + (size_t)hr * HE) + ah * 32;
        const uint32_t dstA = sb + ar2 * A_ROWB + ah * 32;
        const int bk = t >> 3, bs = t & 7;
        const char* srcB = (const char*)(d_wdh + ((size_t)e * HE + bk) * D_HID + bx * 128 + bs * 16);
        const uint32_t dstB = sb + NSTAGE * SLOT_A + bk * B_ROWB + bs * 32;

        float acc[4][4][4] = {};
        const int NC = HE / 32;
#pragma unroll
        for (int s = 0; s < NSTAGE - 1; s++) {
            CPA16(dstA + s * SLOT_A, srcA + s * 64);
            CPA16(dstA + s * SLOT_A + 16, srcA + s * 64 + 16);
            CPA16(dstB + s * SLOT_B, srcB + (size_t)s * 32 * D_HID * 2);
            CPA16(dstB + s * SLOT_B + 16, srcB + (size_t)s * 32 * D_HID * 2 + 16);
            CP_COMMIT();
        }
        for (int kc = 0; kc < NC; kc++) {
            CP_WAIT(NSTAGE - 2);
            __syncthreads();
            const int kn = kc + NSTAGE - 1;
            if (kn < NC) {
                const int sl = kn & (NSTAGE - 1);
                CPA16(dstA + sl * SLOT_A, srcA + kn * 64);
                CPA16(dstA + sl * SLOT_A + 16, srcA + kn * 64 + 16);
                CPA16(dstB + sl * SLOT_B, srcB + (size_t)kn * 32 * D_HID * 2);
                CPA16(dstB + sl * SLOT_B + 16, srcB + (size_t)kn * 32 * D_HID * 2 + 16);
            }
            CP_COMMIT();
            const int cur = kc & (NSTAGE - 1);
            const uint32_t sAc = sb + cur * SLOT_A;
            const uint32_t sBc = sb + NSTAGE * SLOT_A + cur * SLOT_B;
#pragma unroll
            for (int ks = 0; ks < 2; ks++) {
                uint4 a[4]; uint2 b[4];
#pragma unroll
                for (int mi = 0; mi < 4; mi++)
                    LDMX4(a[mi], sAc + (wm * 4 + mi) * (16 * A_ROWB) + ks * 32 + a_off);
#pragma unroll
                for (int j = 0; j < 2; j++) {
                    uint32_t r0, r1, r2, r3;
                    LDMX4T(r0, r1, r2, r3, sBc + ks * (16 * B_ROWB) + (wn * 4 + 2 * j) * 16 + b_off);
                    b[2 * j].x = r0;     b[2 * j].y = r1;
                    b[2 * j + 1].x = r2; b[2 * j + 1].y = r3;
                }
#pragma unroll
                for (int mi = 0; mi < 4; mi++)
#pragma unroll
                    for (int ni = 0; ni < 4; ni++)
                        mma16(acc[mi][ni], a[mi], b[ni]);
            }
        }
        CP_WAIT(0);

        const int q = lane & 3;
#pragma unroll
        for (int mi = 0; mi < 4; mi++) {
            int r1 = row0 + wm * 64 + mi * 16 + (lane >> 2), r2 = r1 + 8;
#pragma unroll
            for (int ni = 0; ni < 4; ni++) {
                int col = bx * 128 + wn * 32 + ni * 8 + 2 * q;
                if (r1 < cnt) {
                    float2 v; v.x = acc[mi][ni][0]; v.y = acc[mi][ni][1];
                    *(float2*)(out + (size_t)d_perm[off + r1] * D_HID + col) = v;
                }
                if (r2 < cnt) {
                    float2 v; v.x = acc[mi][ni][2]; v.y = acc[mi][ni][3];
                    *(float2*)(out + (size_t)d_perm[off + r2] * D_HID + col) = v;
                }
            }
        }
    }
}

// ============================ launch ============================
extern "C" void kernel_launch(void* const* d_in, const int* in_sizes, int n_in,
                              void* d_out, int out_size) {
    const float* x   = (const float*)d_in[0];
    const void*  tok = d_in[1];
    const float* Wg  = (const float*)d_in[2];
    const float* Wu  = (const float*)d_in[3];
    const float* Wd  = (const float*)d_in[4];
    float* out = (float*)d_out;

    static cudaStream_t s1 = nullptr;
    static cudaEvent_t ev0 = nullptr, evWB = nullptr;
    if (!s1) {   // first call is the uncaptured correctness run
        cudaStreamCreateWithFlags(&s1, cudaStreamNonBlocking);
        cudaEventCreateWithFlags(&ev0, cudaEventDisableTiming);
        cudaEventCreateWithFlags(&evWB, cudaEventDisableTiming);
        cudaFuncSetAttribute(fused_kernel, cudaFuncAttributeMaxDynamicSharedMemorySize, SMEM_TOT);
    }

    const int WGU_GRID_HALF = (4 * D_HID * 128) / 256;

    cudaEventRecord(ev0, 0);
    cudaStreamWaitEvent(s1, ev0, 0);

    // s1: route (zeroes flags) -> wgu half B
    route_kernel<<<1, 256, 0, s1>>>(tok);
    conv_wgu_kernel<<<WGU_GRID_HALF, 256, 0, s1>>>(Wg, Wu, 4);
    cudaEventRecord(evWB, s1);

    // stream 0: conv_x, wgu half A, then the fused megakernel
    conv_x_kernel<<<(T_TOKENS * D_HID / 16) / 256, 256>>>(x);
    conv_wgu_kernel<<<WGU_GRID_HALF, 256>>>(Wg, Wu, 0);
    cudaStreamWaitEvent(0, evWB, 0);
    fused_kernel<<<2 * G1_TILES, 256, SMEM_TOT>>>(Wd, out);
}